// round 1
// baseline (speedup 1.0000x reference)
#include <cuda_runtime.h>
#include <math.h>

// Problem constants (fixed shapes per reference)
#define NN 2048
#define KK 14
#define CC 512
#define OO 512
#define EE 78          // all pairs i<j over first 13 nodes
#define BN_EPS 1e-5f

// ---------------- device scratch (no allocations allowed) ----------------
__device__ float g_S1[CC];            // sum over n of 15-unscaled weighted gap sum
__device__ float g_Q[CC];             // sum over n of (13*s2 - s1^2)
__device__ float g_u[CC];             // gamma/sqrt(var+eps)*w_direct
__device__ float g_cst;               // sum_c (beta - mean*g') * w_direct
__device__ float g_agg[(size_t)NN * KK * CC];   // aggregated features (58.7 MB)

// ---------------- kernel 0: zero accumulators ----------------
__global__ void k_zero() {
    int c = threadIdx.x;
    g_S1[c] = 0.f;
    g_Q[c]  = 0.f;
}

// ---------------- kernel 1: per-channel BN statistics ----------------
// grid 256 blocks x 512 threads (1 thread = 1 channel), 8 rows per block
__global__ __launch_bounds__(512) void k_stats(const float* __restrict__ x) {
    int c = threadIdx.x;
    int n0 = blockIdx.x * 8;
    float s1a = 0.f, qa = 0.f;
    for (int r = 0; r < 8; r++) {
        const float* p = x + (size_t)(n0 + r) * (KK * CC) + c;
        float g = p[13 * CC];
        float s1 = 0.f, s2 = 0.f, ws = 0.f;
#pragma unroll
        for (int k = 0; k < 13; k++) {
            float d = fabsf(p[k * CC] - g);
            s1 += d;
            s2 += d * d;
            ws += (float)(12 - 2 * k) * d;
        }
        s1a += ws;
        qa  += 13.f * s2 - s1 * s1;
    }
    atomicAdd(&g_S1[c], s1a);
    atomicAdd(&g_Q[c],  qa);
}

// ---------------- kernel 2: finalize stats, build u[c] and cst ----------------
__global__ __launch_bounds__(512) void k_finalize(const float* __restrict__ gamma,
                                                  const float* __restrict__ beta,
                                                  const float* __restrict__ wdir) {
    int c = threadIdx.x;
    const float inv = 1.f / (float)((size_t)NN * EE);
    float mean = 15.f * g_S1[c] * inv;
    float ms   = 225.f * g_Q[c] * inv;
    float var  = ms - mean * mean;
    float gp   = gamma[c] * rsqrtf(var + BN_EPS);
    float w    = wdir[c];
    float u    = gp * w;
    g_u[c] = u;
    float part = beta[c] * w - mean * u;
    // block reduce 512 -> 1
    __shared__ float sp[16];
    int lane = c & 31, wid = c >> 5;
#pragma unroll
    for (int off = 16; off > 0; off >>= 1)
        part += __shfl_xor_sync(0xffffffffu, part, off);
    if (lane == 0) sp[wid] = part;
    __syncthreads();
    if (c == 0) {
        float s = 0.f;
#pragma unroll
        for (int i = 0; i < 16; i++) s += sp[i];
        g_cst = s;
    }
}

// ---------------- kernel 3: per-sample adjacency + aggregation ----------------
// grid NN blocks x 512 threads (1 thread = 1 channel)
__global__ __launch_bounds__(512) void k_adj(const float* __restrict__ x,
                                             const float* __restrict__ adjin,
                                             const int* __restrict__ ei,
                                             const int* __restrict__ ej) {
    int n = blockIdx.x;
    int c = threadIdx.x;
    int lane = c & 31, warp = c >> 5;

    const float* p = x + (size_t)n * (KK * CC) + c;
    float xv[14];
#pragma unroll
    for (int k = 0; k < 14; k++) xv[k] = p[k * CC];
    float g = xv[13];
    float u = g_u[c];

    __shared__ float pp[16][13];
    __shared__ float sp[13];
    __shared__ float W[14][14];
    __shared__ float rn[14];

    // p_k = sum_c |x_k - x_13| * u[c]  (warp reduce, then cross-warp)
#pragma unroll
    for (int k = 0; k < 13; k++) {
        float v = fabsf(xv[k] - g) * u;
        v += __shfl_xor_sync(0xffffffffu, v, 16);
        v += __shfl_xor_sync(0xffffffffu, v, 8);
        v += __shfl_xor_sync(0xffffffffu, v, 4);
        v += __shfl_xor_sync(0xffffffffu, v, 2);
        v += __shfl_xor_sync(0xffffffffu, v, 1);
        if (lane == 0) pp[warp][k] = v;
    }
    __syncthreads();
    if (c < 13) {
        float s = 0.f;
#pragma unroll
        for (int w2 = 0; w2 < 16; w2++) s += pp[w2][c];
        sp[c] = s;
    }
    if (c < 196) W[c / 14][c % 14] = adjin[c];   // base value 1 * adj
    __syncthreads();
    if (c < EE) {
        int i = ei[c], j = ej[c];
        float z = 15.f * (sp[i] - sp[j]) + g_cst;
        float a = 1.f / (1.f + expf(-4.f * z));
        W[i][j] = 2.f * a * adjin[i * 14 + j];
        W[j][i] = 2.f * (1.f - a) * adjin[j * 14 + i];
    }
    __syncthreads();
    if (c < 14) {
        float s = 0.f;
#pragma unroll
        for (int j = 0; j < 14; j++) s += fabsf(W[c][j]);
        rn[c] = 1.f / fmaxf(s, 1e-12f);
    }
    __syncthreads();

    float* outp = g_agg + (size_t)n * (KK * CC) + c;
#pragma unroll
    for (int i = 0; i < 14; i++) {
        float acc = 0.f;
#pragma unroll
        for (int j = 0; j < 14; j++) acc += W[i][j] * xv[j];
        outp[i * CC] = acc * rn[i];
    }
}

// ---------------- kernel 4: fused dual GEMM + relu epilogue ----------------
// out[m,o] = relu(sum_c agg[m,c]*Wm[o,c]) + sum_c x[m,c]*Wo[o,c]
// M = NN*KK = 28672, tiles 64x64, BK=16, 256 threads, 4x4 micro-tile x2 GEMMs
#define BM 64
#define BNO 64
#define BK 16
#define SPAD 4

__global__ __launch_bounds__(256) void k_gemm(const float* __restrict__ X,
                                              const float* __restrict__ Wm,
                                              const float* __restrict__ Wo,
                                              float* __restrict__ out) {
    __shared__ float sA[BK][BM + SPAD];
    __shared__ float sX[BK][BM + SPAD];
    __shared__ float sM[BK][BNO + SPAD];
    __shared__ float sO[BK][BNO + SPAD];

    const float* AG = g_agg;
    int m0 = blockIdx.x * BM;
    int o0 = blockIdx.y * BNO;
    int tid = threadIdx.x;
    int lrow = tid >> 2;          // 0..63
    int lc4  = (tid & 3) * 4;     // 0,4,8,12
    int tx = tid & 15;            // o dim
    int ty = tid >> 4;            // m dim

    const float* pA = AG + (size_t)(m0 + lrow) * CC + lc4;
    const float* pX = X  + (size_t)(m0 + lrow) * CC + lc4;
    const float* pM = Wm + (size_t)(o0 + lrow) * CC + lc4;
    const float* pO = Wo + (size_t)(o0 + lrow) * CC + lc4;

    float accM[4][4];
    float accO[4][4];
#pragma unroll
    for (int i = 0; i < 4; i++)
#pragma unroll
        for (int j = 0; j < 4; j++) { accM[i][j] = 0.f; accO[i][j] = 0.f; }

    float4 rA = *(const float4*)pA;
    float4 rX = *(const float4*)pX;
    float4 rM = *(const float4*)pM;
    float4 rO = *(const float4*)pO;

    const int NT = CC / BK;   // 32
    for (int t = 0; t < NT; t++) {
        // regs -> shared
        sA[lc4 + 0][lrow] = rA.x; sA[lc4 + 1][lrow] = rA.y;
        sA[lc4 + 2][lrow] = rA.z; sA[lc4 + 3][lrow] = rA.w;
        sX[lc4 + 0][lrow] = rX.x; sX[lc4 + 1][lrow] = rX.y;
        sX[lc4 + 2][lrow] = rX.z; sX[lc4 + 3][lrow] = rX.w;
        sM[lc4 + 0][lrow] = rM.x; sM[lc4 + 1][lrow] = rM.y;
        sM[lc4 + 2][lrow] = rM.z; sM[lc4 + 3][lrow] = rM.w;
        sO[lc4 + 0][lrow] = rO.x; sO[lc4 + 1][lrow] = rO.y;
        sO[lc4 + 2][lrow] = rO.z; sO[lc4 + 3][lrow] = rO.w;
        __syncthreads();

        // prefetch next tile (latency hidden under FFMA below)
        if (t + 1 < NT) {
            int off = (t + 1) * BK;
            rA = *(const float4*)(pA + off);
            rX = *(const float4*)(pX + off);
            rM = *(const float4*)(pM + off);
            rO = *(const float4*)(pO + off);
        }

#pragma unroll
        for (int k = 0; k < BK; k++) {
            float4 av = *(const float4*)&sA[k][ty * 4];
            float4 xv = *(const float4*)&sX[k][ty * 4];
            float4 wm = *(const float4*)&sM[k][tx * 4];
            float4 wo = *(const float4*)&sO[k][tx * 4];
            float ar[4] = {av.x, av.y, av.z, av.w};
            float xr[4] = {xv.x, xv.y, xv.z, xv.w};
            float mr[4] = {wm.x, wm.y, wm.z, wm.w};
            float orr[4] = {wo.x, wo.y, wo.z, wo.w};
#pragma unroll
            for (int i = 0; i < 4; i++)
#pragma unroll
                for (int j = 0; j < 4; j++) {
                    accM[i][j] += ar[i] * mr[j];
                    accO[i][j] += xr[i] * orr[j];
                }
        }
        __syncthreads();
    }

    // epilogue: relu(merged) + original
#pragma unroll
    for (int i = 0; i < 4; i++) {
        float4 v;
        v.x = fmaxf(accM[i][0], 0.f) + accO[i][0];
        v.y = fmaxf(accM[i][1], 0.f) + accO[i][1];
        v.z = fmaxf(accM[i][2], 0.f) + accO[i][2];
        v.w = fmaxf(accM[i][3], 0.f) + accO[i][3];
        *(float4*)&out[(size_t)(m0 + ty * 4 + i) * OO + o0 + tx * 4] = v;
    }
}

// ---------------- launch ----------------
extern "C" void kernel_launch(void* const* d_in, const int* in_sizes, int n_in,
                              void* d_out, int out_size) {
    const float* x     = (const float*)d_in[0];   // (2048,14,512)
    const float* adj   = (const float*)d_in[1];   // (14,14)
    const int*   ei    = (const int*)d_in[2];     // (78,)
    const int*   ej    = (const int*)d_in[3];     // (78,)
    const float* gamma = (const float*)d_in[4];
    const float* beta  = (const float*)d_in[5];
    const float* wdir  = (const float*)d_in[6];
    const float* Wm    = (const float*)d_in[7];   // (512,512)
    const float* Wo    = (const float*)d_in[8];   // (512,512)
    float* out = (float*)d_out;

    k_zero<<<1, CC>>>();
    k_stats<<<NN / 8, CC>>>(x);
    k_finalize<<<1, CC>>>(gamma, beta, wdir);
    k_adj<<<NN, CC>>>(x, adj, ei, ej);
    dim3 grid((NN * KK) / BM, OO / BNO);
    k_gemm<<<grid, 256>>>(x, Wm, Wo, out);
}

// round 3
// speedup vs baseline: 2.6781x; 2.6781x over previous
#include <cuda_runtime.h>
#include <cuda_bf16.h>
#include <cstdint>
#include <stdint.h>
#include <math.h>

// Problem constants (fixed shapes per reference)
#define NN 2048
#define KK 14
#define CC 512
#define OO 512
#define EE 78          // all pairs i<j over first 13 nodes
#define BN_EPS 1e-5f

// ---------------- device scratch (no allocations allowed) ----------------
__device__ float g_S1[CC];
__device__ float g_Q[CC];
__device__ float g_u[CC];
__device__ float g_cst;
__device__ float g_agg[(size_t)NN * KK * CC];   // aggregated features (58.7 MB)

// ---------------- kernel 0: zero accumulators ----------------
__global__ void k_zero() {
    int c = threadIdx.x;
    g_S1[c] = 0.f;
    g_Q[c]  = 0.f;
}

// ---------------- kernel 1: per-channel BN statistics ----------------
__global__ __launch_bounds__(512) void k_stats(const float* __restrict__ x) {
    int c = threadIdx.x;
    int n0 = blockIdx.x * 8;
    float s1a = 0.f, qa = 0.f;
    for (int r = 0; r < 8; r++) {
        const float* p = x + (size_t)(n0 + r) * (KK * CC) + c;
        float g = p[13 * CC];
        float s1 = 0.f, s2 = 0.f, ws = 0.f;
#pragma unroll
        for (int k = 0; k < 13; k++) {
            float d = fabsf(p[k * CC] - g);
            s1 += d;
            s2 += d * d;
            ws += (float)(12 - 2 * k) * d;
        }
        s1a += ws;
        qa  += 13.f * s2 - s1 * s1;
    }
    atomicAdd(&g_S1[c], s1a);
    atomicAdd(&g_Q[c],  qa);
}

// ---------------- kernel 2: finalize stats ----------------
__global__ __launch_bounds__(512) void k_finalize(const float* __restrict__ gamma,
                                                  const float* __restrict__ beta,
                                                  const float* __restrict__ wdir) {
    int c = threadIdx.x;
    const float inv = 1.f / (float)((size_t)NN * EE);
    float mean = 15.f * g_S1[c] * inv;
    float ms   = 225.f * g_Q[c] * inv;
    float var  = ms - mean * mean;
    float gp   = gamma[c] * rsqrtf(var + BN_EPS);
    float w    = wdir[c];
    float u    = gp * w;
    g_u[c] = u;
    float part = beta[c] * w - mean * u;
    __shared__ float sp[16];
    int lane = c & 31, wid = c >> 5;
#pragma unroll
    for (int off = 16; off > 0; off >>= 1)
        part += __shfl_xor_sync(0xffffffffu, part, off);
    if (lane == 0) sp[wid] = part;
    __syncthreads();
    if (c == 0) {
        float s = 0.f;
#pragma unroll
        for (int i = 0; i < 16; i++) s += sp[i];
        g_cst = s;
    }
}

// ---------------- kernel 3: per-sample adjacency + aggregation ----------------
__global__ __launch_bounds__(512) void k_adj(const float* __restrict__ x,
                                             const float* __restrict__ adjin,
                                             const int* __restrict__ ei,
                                             const int* __restrict__ ej) {
    int n = blockIdx.x;
    int c = threadIdx.x;
    int lane = c & 31, warp = c >> 5;

    const float* p = x + (size_t)n * (KK * CC) + c;
    float xv[14];
#pragma unroll
    for (int k = 0; k < 14; k++) xv[k] = p[k * CC];
    float g = xv[13];
    float u = g_u[c];

    __shared__ float pp[16][13];
    __shared__ float sp[13];
    __shared__ float W[14][14];
    __shared__ float rn[14];

#pragma unroll
    for (int k = 0; k < 13; k++) {
        float v = fabsf(xv[k] - g) * u;
        v += __shfl_xor_sync(0xffffffffu, v, 16);
        v += __shfl_xor_sync(0xffffffffu, v, 8);
        v += __shfl_xor_sync(0xffffffffu, v, 4);
        v += __shfl_xor_sync(0xffffffffu, v, 2);
        v += __shfl_xor_sync(0xffffffffu, v, 1);
        if (lane == 0) pp[warp][k] = v;
    }
    __syncthreads();
    if (c < 13) {
        float s = 0.f;
#pragma unroll
        for (int w2 = 0; w2 < 16; w2++) s += pp[w2][c];
        sp[c] = s;
    }
    if (c < 196) W[c / 14][c % 14] = adjin[c];
    __syncthreads();
    if (c < EE) {
        int i = ei[c], j = ej[c];
        float z = 15.f * (sp[i] - sp[j]) + g_cst;
        float a = 1.f / (1.f + expf(-4.f * z));
        W[i][j] = 2.f * a * adjin[i * 14 + j];
        W[j][i] = 2.f * (1.f - a) * adjin[j * 14 + i];
    }
    __syncthreads();
    if (c < 14) {
        float s = 0.f;
#pragma unroll
        for (int j = 0; j < 14; j++) s += fabsf(W[c][j]);
        rn[c] = 1.f / fmaxf(s, 1e-12f);
    }
    __syncthreads();

    float* outp = g_agg + (size_t)n * (KK * CC) + c;
#pragma unroll
    for (int i = 0; i < 14; i++) {
        float acc = 0.f;
#pragma unroll
        for (int j = 0; j < 14; j++) acc += W[i][j] * xv[j];
        outp[i * CC] = acc * rn[i];
    }
}

// ---------------- kernel 4: bf16x3 tensor-core GEMM ----------------
// C[m,o] = sum_c A[m,c]*W[o,c], A split into bf16 hi/lo (Dekker), 3 MMA products.
// Block tile 128x128, BK=16, 8 warps (2x4), warp tile 64x32, mma.m16n8k16.bf16.
#define GM 128
#define GN 128
#define GK 16
#define SSTR 12   // padded uint32 stride (8 data + 4 pad) -> conflict-free frag LDS

__device__ __forceinline__ void split_pack(float fx, float fy, uint32_t &h, uint32_t &l) {
    __nv_bfloat162 bh = __float22bfloat162_rn(make_float2(fx, fy));
    float2 hf = __bfloat1622float2(bh);
    __nv_bfloat162 bl = __float22bfloat162_rn(make_float2(fx - hf.x, fy - hf.y));
    h = *reinterpret_cast<uint32_t*>(&bh);
    l = *reinterpret_cast<uint32_t*>(&bl);
}

#define MMA_BF16(Cr, A0, A1, A2, A3, B0, B1)                                \
    asm volatile("mma.sync.aligned.m16n8k16.row.col.f32.bf16.bf16.f32 "      \
                 "{%0,%1,%2,%3}, {%4,%5,%6,%7}, {%8,%9}, {%0,%1,%2,%3};\n"   \
                 : "+f"(Cr[0]), "+f"(Cr[1]), "+f"(Cr[2]), "+f"(Cr[3])        \
                 : "r"(A0), "r"(A1), "r"(A2), "r"(A3), "r"(B0), "r"(B1))

template <bool MERGED>
__global__ __launch_bounds__(256) void k_gemm_tc(const float* __restrict__ X,
                                                 const float* __restrict__ W,
                                                 float* __restrict__ out) {
    const float* A = MERGED ? (const float*)g_agg : X;

    __shared__ uint32_t sAh[GM][SSTR];
    __shared__ uint32_t sAl[GM][SSTR];
    __shared__ uint32_t sBh[GN][SSTR];
    __shared__ uint32_t sBl[GN][SSTR];

    int m0 = blockIdx.x * GM;
    int o0 = blockIdx.y * GN;
    int tid  = threadIdx.x;
    int warp = tid >> 5, lane = tid & 31;
    int gid = lane >> 2, tig = lane & 3;
    int wm = warp & 1;       // 0..1  (m dim, 64 each)
    int wn = warp >> 1;      // 0..3  (n dim, 32 each)

    int lr  = tid >> 2;        // 0..63 loader row
    int kc  = (tid & 3) * 4;   // float col within 16
    int kc2 = (tid & 3) * 2;   // packed uint32 col

    const float* pA0 = A + (size_t)(m0 + lr) * CC + kc;
    const float* pA1 = A + (size_t)(m0 + lr + 64) * CC + kc;
    const float* pB0 = W + (size_t)(o0 + lr) * CC + kc;
    const float* pB1 = W + (size_t)(o0 + lr + 64) * CC + kc;

    float acc[4][4][4];
#pragma unroll
    for (int mt = 0; mt < 4; mt++)
#pragma unroll
        for (int nt = 0; nt < 4; nt++)
#pragma unroll
            for (int i = 0; i < 4; i++) acc[mt][nt][i] = 0.f;

    float4 ra0 = *(const float4*)pA0;
    float4 ra1 = *(const float4*)pA1;
    float4 rb0 = *(const float4*)pB0;
    float4 rb1 = *(const float4*)pB1;

    const int NT = CC / GK;   // 32
    for (int t = 0; t < NT; t++) {
        __syncthreads();   // previous tile fully consumed
        uint32_t h, l;
        split_pack(ra0.x, ra0.y, h, l); sAh[lr][kc2] = h;        sAl[lr][kc2] = l;
        split_pack(ra0.z, ra0.w, h, l); sAh[lr][kc2 + 1] = h;    sAl[lr][kc2 + 1] = l;
        split_pack(ra1.x, ra1.y, h, l); sAh[lr + 64][kc2] = h;   sAl[lr + 64][kc2] = l;
        split_pack(ra1.z, ra1.w, h, l); sAh[lr + 64][kc2 + 1] = h; sAl[lr + 64][kc2 + 1] = l;
        split_pack(rb0.x, rb0.y, h, l); sBh[lr][kc2] = h;        sBl[lr][kc2] = l;
        split_pack(rb0.z, rb0.w, h, l); sBh[lr][kc2 + 1] = h;    sBl[lr][kc2 + 1] = l;
        split_pack(rb1.x, rb1.y, h, l); sBh[lr + 64][kc2] = h;   sBl[lr + 64][kc2] = l;
        split_pack(rb1.z, rb1.w, h, l); sBh[lr + 64][kc2 + 1] = h; sBl[lr + 64][kc2 + 1] = l;
        __syncthreads();

        // prefetch next tile (LDG latency hidden under tensor work below)
        if (t + 1 < NT) {
            int off = (t + 1) * GK;
            ra0 = *(const float4*)(pA0 + off);
            ra1 = *(const float4*)(pA1 + off);
            rb0 = *(const float4*)(pB0 + off);
            rb1 = *(const float4*)(pB1 + off);
        }

        uint32_t bh[4][2], bl[4][2];
#pragma unroll
        for (int nt = 0; nt < 4; nt++) {
            int br = wn * 32 + nt * 8 + gid;
            bh[nt][0] = sBh[br][tig];     bh[nt][1] = sBh[br][tig + 4];
            bl[nt][0] = sBl[br][tig];     bl[nt][1] = sBl[br][tig + 4];
        }
#pragma unroll
        for (int mt = 0; mt < 4; mt++) {
            int ar = wm * 64 + mt * 16 + gid;
            uint32_t ah0 = sAh[ar][tig],     ah1 = sAh[ar + 8][tig];
            uint32_t ah2 = sAh[ar][tig + 4], ah3 = sAh[ar + 8][tig + 4];
            uint32_t al0 = sAl[ar][tig],     al1 = sAl[ar + 8][tig];
            uint32_t al2 = sAl[ar][tig + 4], al3 = sAl[ar + 8][tig + 4];
#pragma unroll
            for (int nt = 0; nt < 4; nt++) {
                MMA_BF16(acc[mt][nt], ah0, ah1, ah2, ah3, bh[nt][0], bh[nt][1]);
                MMA_BF16(acc[mt][nt], ah0, ah1, ah2, ah3, bl[nt][0], bl[nt][1]);
                MMA_BF16(acc[mt][nt], al0, al1, al2, al3, bh[nt][0], bh[nt][1]);
            }
        }
    }

    // epilogue
#pragma unroll
    for (int mt = 0; mt < 4; mt++) {
#pragma unroll
        for (int nt = 0; nt < 4; nt++) {
            int row = m0 + wm * 64 + mt * 16 + gid;
            int col = o0 + wn * 32 + nt * 8 + 2 * tig;
            float* p0 = &out[(size_t)row * OO + col];
            float* p1 = &out[(size_t)(row + 8) * OO + col];
            if (MERGED) {
                float2 o0v = *(float2*)p0;
                float2 o1v = *(float2*)p1;
                o0v.x += fmaxf(acc[mt][nt][0], 0.f);
                o0v.y += fmaxf(acc[mt][nt][1], 0.f);
                o1v.x += fmaxf(acc[mt][nt][2], 0.f);
                o1v.y += fmaxf(acc[mt][nt][3], 0.f);
                *(float2*)p0 = o0v;
                *(float2*)p1 = o1v;
            } else {
                *(float2*)p0 = make_float2(acc[mt][nt][0], acc[mt][nt][1]);
                *(float2*)p1 = make_float2(acc[mt][nt][2], acc[mt][nt][3]);
            }
        }
    }
}

// ---------------- launch ----------------
extern "C" void kernel_launch(void* const* d_in, const int* in_sizes, int n_in,
                              void* d_out, int out_size) {
    const float* x     = (const float*)d_in[0];   // (2048,14,512)
    const float* adj   = (const float*)d_in[1];   // (14,14)
    const int*   ei    = (const int*)d_in[2];     // (78,)
    const int*   ej    = (const int*)d_in[3];     // (78,)
    const float* gamma = (const float*)d_in[4];
    const float* beta  = (const float*)d_in[5];
    const float* wdir  = (const float*)d_in[6];
    const float* Wm    = (const float*)d_in[7];   // (512,512)
    const float* Wo    = (const float*)d_in[8];   // (512,512)
    float* out = (float*)d_out;

    k_zero<<<1, CC>>>();
    k_stats<<<NN / 8, CC>>>(x);
    k_finalize<<<1, CC>>>(gamma, beta, wdir);
    k_adj<<<NN, CC>>>(x, adj, ei, ej);

    dim3 grid((NN * KK) / GM, OO / GN);   // 224 x 4
    k_gemm_tc<false><<<grid, 256>>>(x, Wo, out);   // out  = x   @ Wo^T
    k_gemm_tc<true ><<<grid, 256>>>(x, Wm, out);   // out += relu(agg @ Wm^T)
}